// round 9
// baseline (speedup 1.0000x reference)
#include <cuda_runtime.h>
#include <cstdint>

// B=8, M=512, A=16, F=128. Dense register-resident contraction:
//   out[d,f] = sum_c ( sum_a cgc[a,d,c] * x[a,f] ) * y[c,f]
// One warp owns a full (b,m) tile (128 f = 2 f32x2 per lane). The d-range is
// split into 2 passes of 8 (acc regs halved -> 4 blocks/SM = 16 warps/SM);
// each pass re-streams y from gmem (register double-buffered). Coefficient
// LDS count is unchanged: each pass reads only its own d-half of gpair.

#define AA 16
#define FF 128
#define TILE_FLOATS (AA * FF)    // 2048
#define WARPS_PER_BLOCK 4
#define THREADS 128
#define DPP 8                    // d's per pass
#define NPASS 2

typedef unsigned long long ull;

__device__ __forceinline__ ull fma2(ull a, ull b, ull c) {
    ull d;
    asm("fma.rn.f32x2 %0, %1, %2, %3;" : "=l"(d) : "l"(a), "l"(b), "l"(c));
    return d;
}

__global__ __launch_bounds__(THREADS, 4) void tp_dense_kernel(
    const float* __restrict__ x,
    const float* __restrict__ y,
    const float* __restrict__ cgc,
    float* __restrict__ out)
{
    // cgc re-laid-out as [c][d][a], each coefficient duplicated {g,g} -> 32 KB
    __shared__ __align__(16) ull gpair[AA * AA * AA];

    const int tid = threadIdx.x;

    // Stage + transpose + duplicate cgc (dest index i = c*256 + d*16 + a)
#pragma unroll
    for (int i = tid; i < AA * AA * AA; i += THREADS) {
        const int c = i >> 8;
        const int d = (i >> 4) & 15;
        const int a = i & 15;
        const unsigned int bits = __float_as_uint(cgc[a * 256 + d * 16 + c]);
        gpair[i] = ((ull)bits << 32) | bits;
    }

    const int wid  = tid >> 5;
    const int lane = tid & 31;
    const int bm   = blockIdx.x * WARPS_PER_BLOCK + wid;

    // x tile -> registers: lane holds float2 slots {lane, lane+32} of each row
    const ull* xg = (const ull*)(x + (size_t)bm * TILE_FLOATS);
    ull x0[AA], x1[AA];
#pragma unroll
    for (int a = 0; a < AA; ++a) {
        x0[a] = xg[a * 64 + lane];
        x1[a] = xg[a * 64 + 32 + lane];
    }

    __syncthreads();

    const ull* yg = (const ull*)(y + (size_t)bm * TILE_FLOATS);
    ull*       og = (ull*)(out + (size_t)bm * TILE_FLOATS);

#pragma unroll 1
    for (int pass = 0; pass < NPASS; ++pass) {
        const int dbase = pass * DPP;

        ull acc0[DPP], acc1[DPP];
#pragma unroll
        for (int dd = 0; dd < DPP; ++dd) { acc0[dd] = 0ull; acc1[dd] = 0ull; }

        // y double-buffer (branchless wrapped prefetch)
        ull yn0 = yg[lane];
        ull yn1 = yg[32 + lane];

#pragma unroll 1
        for (int c = 0; c < AA; ++c) {
            const ull yv0 = yn0;
            const ull yv1 = yn1;
            const int cn = (c + 1) & 15;
            yn0 = yg[cn * 64 + lane];
            yn1 = yg[cn * 64 + 32 + lane];

            const ulonglong2* g2 =
                (const ulonglong2*)(gpair + c * 256 + dbase * AA);

#pragma unroll
            for (int dd = 0; dd < DPP; ++dd) {
                const ulonglong2* gd = g2 + dd * 8;
                ull t0 = 0ull, t1 = 0ull;
#pragma unroll
                for (int a2 = 0; a2 < 8; ++a2) {
                    const ulonglong2 gg = gd[a2];   // LDS.128: 2 dup'd coeffs
                    t0 = fma2(gg.x, x0[a2 * 2],     t0);
                    t1 = fma2(gg.x, x1[a2 * 2],     t1);
                    t0 = fma2(gg.y, x0[a2 * 2 + 1], t0);
                    t1 = fma2(gg.y, x1[a2 * 2 + 1], t1);
                }
                acc0[dd] = fma2(t0, yv0, acc0[dd]);
                acc1[dd] = fma2(t1, yv1, acc1[dd]);
            }
        }

#pragma unroll
        for (int dd = 0; dd < DPP; ++dd) {
            og[(dbase + dd) * 64 + lane]      = acc0[dd];
            og[(dbase + dd) * 64 + 32 + lane] = acc1[dd];
        }
    }
}

extern "C" void kernel_launch(void* const* d_in, const int* in_sizes, int n_in,
                              void* d_out, int out_size) {
    const float* x   = (const float*)d_in[0];
    const float* y   = (const float*)d_in[1];
    const float* cgc = (const float*)d_in[2];
    float* out = (float*)d_out;

    const int n_bm = in_sizes[0] / TILE_FLOATS;          // 4096
    const int grid = n_bm / WARPS_PER_BLOCK;             // 1024

    tp_dense_kernel<<<grid, THREADS>>>(x, y, cgc, out);
}

// round 11
// speedup vs baseline: 1.0344x; 1.0344x over previous
#include <cuda_runtime.h>
#include <cstdint>

// B=8, M=512, A=16, F=128. Dense register-resident contraction:
//   out[d,f] = sum_c ( sum_a cgc[a,d,c] * x[a,f] ) * y[c,f]
// One warp owns a full (b,m) tile (128 f = 2 f32x2 per lane).
// d processed in PAIRS -> 4 independent FFMA2 chains (t0A,t1A,t0B,t1B),
// dependency distance 4 = FFMA latency -> full issue density, no extra ops.
// Coefficients duplicated {g,g} in smem, warp-uniform LDS.128.

#define AA 16
#define FF 128
#define TILE_FLOATS (AA * FF)    // 2048
#define WARPS_PER_BLOCK 4
#define THREADS 128

typedef unsigned long long ull;

__device__ __forceinline__ ull fma2(ull a, ull b, ull c) {
    ull d;
    asm("fma.rn.f32x2 %0, %1, %2, %3;" : "=l"(d) : "l"(a), "l"(b), "l"(c));
    return d;
}

__global__ __launch_bounds__(THREADS, 3) void tp_dense_kernel(
    const float* __restrict__ x,
    const float* __restrict__ y,
    const float* __restrict__ cgc,
    float* __restrict__ out)
{
    // cgc re-laid-out as [c][d][a], each coefficient duplicated {g,g} -> 32 KB
    __shared__ __align__(16) ull gpair[AA * AA * AA];

    const int tid = threadIdx.x;

    // Stage + transpose + duplicate cgc (dest index i = c*256 + d*16 + a)
#pragma unroll
    for (int i = tid; i < AA * AA * AA; i += THREADS) {
        const int c = i >> 8;
        const int d = (i >> 4) & 15;
        const int a = i & 15;
        const unsigned int bits = __float_as_uint(cgc[a * 256 + d * 16 + c]);
        gpair[i] = ((ull)bits << 32) | bits;
    }

    const int wid  = tid >> 5;
    const int lane = tid & 31;
    const int bm   = blockIdx.x * WARPS_PER_BLOCK + wid;

    // x tile -> registers: lane holds float2 slots {lane, lane+32} of each row
    const ull* xg = (const ull*)(x + (size_t)bm * TILE_FLOATS);
    ull x0[AA], x1[AA];
#pragma unroll
    for (int a = 0; a < AA; ++a) {
        x0[a] = xg[a * 64 + lane];
        x1[a] = xg[a * 64 + 32 + lane];
    }

    ull acc0[AA], acc1[AA];
#pragma unroll
    for (int d = 0; d < AA; ++d) { acc0[d] = 0ull; acc1[d] = 0ull; }

    __syncthreads();

    const ull* yg = (const ull*)(y + (size_t)bm * TILE_FLOATS);

#pragma unroll 1
    for (int c = 0; c < AA; ++c) {
        const ull yv0 = yg[c * 64 + lane];
        const ull yv1 = yg[c * 64 + 32 + lane];
        const ulonglong2* g2 = (const ulonglong2*)(gpair + c * 256);

        // d-pair loop: 4 independent chains, dep distance = 4 instr = FFMA lat
#pragma unroll
        for (int dp = 0; dp < AA / 2; ++dp) {
            const ulonglong2* gdA = g2 + (dp * 2) * 8;
            const ulonglong2* gdB = gdA + 8;
            ull t0A = 0ull, t1A = 0ull, t0B = 0ull, t1B = 0ull;
#pragma unroll
            for (int a2 = 0; a2 < 8; ++a2) {
                const ulonglong2 ggA = gdA[a2];   // 2 dup'd coeffs for d=2dp
                const ulonglong2 ggB = gdB[a2];   // 2 dup'd coeffs for d=2dp+1
                t0A = fma2(ggA.x, x0[a2 * 2],     t0A);
                t1A = fma2(ggA.x, x1[a2 * 2],     t1A);
                t0B = fma2(ggB.x, x0[a2 * 2],     t0B);
                t1B = fma2(ggB.x, x1[a2 * 2],     t1B);
                t0A = fma2(ggA.y, x0[a2 * 2 + 1], t0A);
                t1A = fma2(ggA.y, x1[a2 * 2 + 1], t1A);
                t0B = fma2(ggB.y, x0[a2 * 2 + 1], t0B);
                t1B = fma2(ggB.y, x1[a2 * 2 + 1], t1B);
            }
            acc0[dp * 2]     = fma2(t0A, yv0, acc0[dp * 2]);
            acc1[dp * 2]     = fma2(t1A, yv1, acc1[dp * 2]);
            acc0[dp * 2 + 1] = fma2(t0B, yv0, acc0[dp * 2 + 1]);
            acc1[dp * 2 + 1] = fma2(t1B, yv1, acc1[dp * 2 + 1]);
        }
    }

    ull* og = (ull*)(out + (size_t)bm * TILE_FLOATS);
#pragma unroll
    for (int d = 0; d < AA; ++d) {
        og[d * 64 + lane]      = acc0[d];
        og[d * 64 + 32 + lane] = acc1[d];
    }
}

extern "C" void kernel_launch(void* const* d_in, const int* in_sizes, int n_in,
                              void* d_out, int out_size) {
    const float* x   = (const float*)d_in[0];
    const float* y   = (const float*)d_in[1];
    const float* cgc = (const float*)d_in[2];
    float* out = (float*)d_out;

    const int n_bm = in_sizes[0] / TILE_FLOATS;          // 4096
    const int grid = n_bm / WARPS_PER_BLOCK;             // 1024

    tp_dense_kernel<<<grid, THREADS>>>(x, y, cgc, out);
}

// round 12
// speedup vs baseline: 1.2471x; 1.2056x over previous
#include <cuda_runtime.h>
#include <cstdint>

// B=8, M=512, A=16, F=128. Dense register-resident contraction:
//   out[d,f] = sum_c y[c,f] * ( sum_a cgc[a,d,c] * x[a,f] )
// d-PACKED coefficient scheme: smem holds {g[a,2dp,c], g[a,2dp+1,c]} pairs
// (no duplication -> 1 LDS.128 = 4 coefficients, total LDS halved to 4.2M).
// x is duplicated {x_f,x_f} into 64 persistent ull regs per warp-tile;
// acc packs d-pairs. 1 LDS per 8 FFMA2 -> FMA-dense stream.
// Persistent grid: 296 blocks (2/SM), cgc staged once per block.

#define AA 16
#define FF 128
#define TILE_FLOATS 2048
#define THREADS 128
#define GRID_BLOCKS 296            // 148 SMs x 2 blocks
#define WSLOTS (GRID_BLOCKS * 4)   // persistent warp slots

typedef unsigned long long ull;

__device__ __forceinline__ ull fma2(ull a, ull b, ull c) {
    ull d;
    asm("fma.rn.f32x2 %0, %1, %2, %3;" : "=l"(d) : "l"(a), "l"(b), "l"(c));
    return d;
}
__device__ __forceinline__ ull dup32(float v) {
    unsigned int u = __float_as_uint(v);
    return ((ull)u << 32) | u;
}
__device__ __forceinline__ float ulo(ull v) {
    return __uint_as_float((unsigned int)v);
}
__device__ __forceinline__ float uhi(ull v) {
    return __uint_as_float((unsigned int)(v >> 32));
}

__global__ __launch_bounds__(THREADS, 2) void tp_dense_kernel(
    const float* __restrict__ x,
    const float* __restrict__ y,
    const float* __restrict__ cgc,
    float* __restrict__ out,
    int n_bm)
{
    // Staged cgc, d-pair packed: gdpk[c][dp][a] = {g[a,2dp,c], g[a,2dp+1,c]}
    __shared__ float sc[AA * AA * AA];          // 16 KB linear copy
    __shared__ __align__(16) ull gdpk[2048];    // 16 KB packed

    const int tid = threadIdx.x;

    // Coalesced linear copy of cgc, then packed scatter (once per block)
#pragma unroll
    for (int j = tid; j < AA * AA * AA; j += THREADS) sc[j] = cgc[j];
    __syncthreads();
#pragma unroll
    for (int s = tid; s < 2048; s += THREADS) {
        const int c  = s >> 7;
        const int dp = (s >> 4) & 7;
        const int a  = s & 15;
        const unsigned int lo = __float_as_uint(sc[a * 256 + dp * 32 + c]);
        const unsigned int hi = __float_as_uint(sc[a * 256 + dp * 32 + 16 + c]);
        gdpk[s] = ((ull)hi << 32) | lo;
    }
    __syncthreads();

    const int wid   = tid >> 5;
    const int lane  = tid & 31;
    const int wslot = blockIdx.x * 4 + wid;

    // Persistent: each warp loops over tiles. No block syncs below.
    for (int bm = wslot; bm < n_bm; bm += WSLOTS) {
        const float4* xg4 = (const float4*)(x + (size_t)bm * TILE_FLOATS);
        const float4* yg4 = (const float4*)(y + (size_t)bm * TILE_FLOATS);
        float4*       og4 = (float4*)(out + (size_t)bm * TILE_FLOATS);

        // x tile -> duplicated registers: lane owns f = 4*lane..4*lane+3
        // xd[a*4 + k] = {x[a, 4l+k], x[a, 4l+k]}
        ull xd[AA * 4];
#pragma unroll
        for (int a = 0; a < AA; ++a) {
            const float4 xv = xg4[a * 32 + lane];
            xd[a * 4 + 0] = dup32(xv.x);
            xd[a * 4 + 1] = dup32(xv.y);
            xd[a * 4 + 2] = dup32(xv.z);
            xd[a * 4 + 3] = dup32(xv.w);
        }

        // acc packs d-pairs: acc[dp*4+k] = {out[2dp, f_k], out[2dp+1, f_k]}
        ull acc[8 * 4];
#pragma unroll
        for (int i = 0; i < 32; ++i) acc[i] = 0ull;

        // y double-buffer across c
        float4 yv = yg4[lane];

#pragma unroll 1
        for (int c = 0; c < AA; ++c) {
            const ull yd0 = dup32(yv.x);
            const ull yd1 = dup32(yv.y);
            const ull yd2 = dup32(yv.z);
            const ull yd3 = dup32(yv.w);
            yv = yg4[((c + 1) & 15) * 32 + lane];   // prefetch next c

            const ulonglong2* gc = (const ulonglong2*)(gdpk + c * 128);

#pragma unroll
            for (int dp = 0; dp < 8; ++dp) {
                const ulonglong2* gp = gc + dp * 8;
                ull t0 = 0ull, t1 = 0ull, t2 = 0ull, t3 = 0ull;
#pragma unroll
                for (int a2 = 0; a2 < 8; ++a2) {
                    const ulonglong2 gg = gp[a2];  // 4 coeffs: a=2a2,2a2+1 x {d0,d1}
                    t0 = fma2(gg.x, xd[(a2 * 2) * 4 + 0], t0);
                    t1 = fma2(gg.x, xd[(a2 * 2) * 4 + 1], t1);
                    t2 = fma2(gg.x, xd[(a2 * 2) * 4 + 2], t2);
                    t3 = fma2(gg.x, xd[(a2 * 2) * 4 + 3], t3);
                    t0 = fma2(gg.y, xd[(a2 * 2 + 1) * 4 + 0], t0);
                    t1 = fma2(gg.y, xd[(a2 * 2 + 1) * 4 + 1], t1);
                    t2 = fma2(gg.y, xd[(a2 * 2 + 1) * 4 + 2], t2);
                    t3 = fma2(gg.y, xd[(a2 * 2 + 1) * 4 + 3], t3);
                }
                acc[dp * 4 + 0] = fma2(t0, yd0, acc[dp * 4 + 0]);
                acc[dp * 4 + 1] = fma2(t1, yd1, acc[dp * 4 + 1]);
                acc[dp * 4 + 2] = fma2(t2, yd2, acc[dp * 4 + 2]);
                acc[dp * 4 + 3] = fma2(t3, yd3, acc[dp * 4 + 3]);
            }
        }

        // Epilogue: unpack d-pairs -> two float4 rows per dp
#pragma unroll
        for (int dp = 0; dp < 8; ++dp) {
            const float4 o0 = make_float4(ulo(acc[dp * 4 + 0]), ulo(acc[dp * 4 + 1]),
                                          ulo(acc[dp * 4 + 2]), ulo(acc[dp * 4 + 3]));
            const float4 o1 = make_float4(uhi(acc[dp * 4 + 0]), uhi(acc[dp * 4 + 1]),
                                          uhi(acc[dp * 4 + 2]), uhi(acc[dp * 4 + 3]));
            og4[(dp * 2) * 32 + lane]     = o0;
            og4[(dp * 2 + 1) * 32 + lane] = o1;
        }
    }
}

extern "C" void kernel_launch(void* const* d_in, const int* in_sizes, int n_in,
                              void* d_out, int out_size) {
    const float* x   = (const float*)d_in[0];
    const float* y   = (const float*)d_in[1];
    const float* cgc = (const float*)d_in[2];
    float* out = (float*)d_out;

    const int n_bm = in_sizes[0] / TILE_FLOATS;   // 4096

    tp_dense_kernel<<<GRID_BLOCKS, THREADS>>>(x, y, cgc, out, n_bm);
}

// round 13
// speedup vs baseline: 1.3884x; 1.1133x over previous
#include <cuda_runtime.h>
#include <cstdint>

// B=8, M=512, A=16, F=128. Dense register-resident contraction:
//   out[d,f] = sum_c y[c,f] * ( sum_a cgc[a,d,c] * x[a,f] )
// d-PACKED coefficients: one LDS.128 = 4 coefficients ({d0,d1} x 2 a's).
// x duplicated {x,x} into 128 persistent regs per warp-tile.
// dp split into 2 passes of 4 (acc halved); explicit A/B coefficient
// double-buffer keeps LDS one group (~16+ cyc) ahead of consumption.
// Persistent grid: 296 blocks (2/SM), cgc staged once per block.

#define AA 16
#define TILE_FLOATS 2048
#define THREADS 128
#define GRID_BLOCKS 296
#define WSLOTS (GRID_BLOCKS * 4)

typedef unsigned long long ull;

__device__ __forceinline__ ull fma2(ull a, ull b, ull c) {
    ull d;
    asm("fma.rn.f32x2 %0, %1, %2, %3;" : "=l"(d) : "l"(a), "l"(b), "l"(c));
    return d;
}
__device__ __forceinline__ ull dup32(float v) {
    unsigned int u = __float_as_uint(v);
    return ((ull)u << 32) | u;
}
__device__ __forceinline__ float ulo(ull v) { return __uint_as_float((unsigned int)v); }
__device__ __forceinline__ float uhi(ull v) { return __uint_as_float((unsigned int)(v >> 32)); }

// load a 4-entry coefficient group (4 x LDS.128)
#define LOADQ(buf, base)            \
    {                               \
        buf[0] = gc[(base) + 0];    \
        buf[1] = gc[(base) + 1];    \
        buf[2] = gc[(base) + 2];    \
        buf[3] = gc[(base) + 3];    \
    }

// 32 FFMA2 consuming one 4-entry group; ab = a-base (0 or 8)
#define FMAG(buf, ab)                                       \
    {                                                       \
        _Pragma("unroll")                                   \
        for (int q = 0; q < 4; ++q) {                       \
            const ulonglong2 gg = buf[q];                   \
            const int a0 = ((ab) + q * 2) * 4;              \
            const int a1 = ((ab) + q * 2 + 1) * 4;          \
            t0 = fma2(gg.x, xd[a0 + 0], t0);                \
            t1 = fma2(gg.x, xd[a0 + 1], t1);                \
            t2 = fma2(gg.x, xd[a0 + 2], t2);                \
            t3 = fma2(gg.x, xd[a0 + 3], t3);                \
            t0 = fma2(gg.y, xd[a1 + 0], t0);                \
            t1 = fma2(gg.y, xd[a1 + 1], t1);                \
            t2 = fma2(gg.y, xd[a1 + 2], t2);                \
            t3 = fma2(gg.y, xd[a1 + 3], t3);                \
        }                                                   \
    }

// fold t into acc for local d-pair dpl, then reset t
#define ACCUM(dpl)                                          \
    {                                                       \
        acc[(dpl) * 4 + 0] = fma2(t0, yd0, acc[(dpl) * 4 + 0]); \
        acc[(dpl) * 4 + 1] = fma2(t1, yd1, acc[(dpl) * 4 + 1]); \
        acc[(dpl) * 4 + 2] = fma2(t2, yd2, acc[(dpl) * 4 + 2]); \
        acc[(dpl) * 4 + 3] = fma2(t3, yd3, acc[(dpl) * 4 + 3]); \
        t0 = t1 = t2 = t3 = 0ull;                           \
    }

__global__ __launch_bounds__(THREADS, 2) void tp_dense_kernel(
    const float* __restrict__ x,
    const float* __restrict__ y,
    const float* __restrict__ cgc,
    float* __restrict__ out,
    int n_bm)
{
    // Staged cgc, d-pair packed: gdpk[c][dp][a] = {g[a,2dp,c], g[a,2dp+1,c]}
    __shared__ float sc[AA * AA * AA];          // 16 KB linear copy
    __shared__ __align__(16) ull gdpk[2048];    // 16 KB packed

    const int tid = threadIdx.x;

#pragma unroll
    for (int j = tid; j < AA * AA * AA; j += THREADS) sc[j] = cgc[j];
    __syncthreads();
#pragma unroll
    for (int s = tid; s < 2048; s += THREADS) {
        const int c  = s >> 7;
        const int dp = (s >> 4) & 7;
        const int a  = s & 15;
        const unsigned int lo = __float_as_uint(sc[a * 256 + dp * 32 + c]);
        const unsigned int hi = __float_as_uint(sc[a * 256 + dp * 32 + 16 + c]);
        gdpk[s] = ((ull)hi << 32) | lo;
    }
    __syncthreads();

    const int wid   = tid >> 5;
    const int lane  = tid & 31;
    const int wslot = blockIdx.x * 4 + wid;

    for (int bm = wslot; bm < n_bm; bm += WSLOTS) {
        const float4* xg4 = (const float4*)(x + (size_t)bm * TILE_FLOATS);
        const float4* yg4 = (const float4*)(y + (size_t)bm * TILE_FLOATS);
        float4*       og4 = (float4*)(out + (size_t)bm * TILE_FLOATS);

        // x tile -> duplicated regs (persists across both dp passes)
        ull xd[AA * 4];
#pragma unroll
        for (int a = 0; a < AA; ++a) {
            const float4 xv = xg4[a * 32 + lane];
            xd[a * 4 + 0] = dup32(xv.x);
            xd[a * 4 + 1] = dup32(xv.y);
            xd[a * 4 + 2] = dup32(xv.z);
            xd[a * 4 + 3] = dup32(xv.w);
        }

#pragma unroll 1
        for (int pass = 0; pass < 2; ++pass) {
            const int dbase = pass * 4;   // dp base for this pass

            ull acc[16];
#pragma unroll
            for (int i = 0; i < 16; ++i) acc[i] = 0ull;

            float4 yv = yg4[lane];

#pragma unroll 1
            for (int c = 0; c < AA; ++c) {
                const ull yd0 = dup32(yv.x);
                const ull yd1 = dup32(yv.y);
                const ull yd2 = dup32(yv.z);
                const ull yd3 = dup32(yv.w);
                yv = yg4[((c + 1) & 15) * 32 + lane];   // prefetch next c

                const ulonglong2* gc =
                    (const ulonglong2*)(gdpk + c * 128 + dbase * 16);

                ulonglong2 bufA[4], bufB[4];
                ull t0 = 0ull, t1 = 0ull, t2 = 0ull, t3 = 0ull;

                // software pipeline: load group g+1 while FMAing group g
                LOADQ(bufA, 0);
                LOADQ(bufB, 4);   FMAG(bufA, 0);
                LOADQ(bufA, 8);   FMAG(bufB, 8);  ACCUM(0);
                LOADQ(bufB, 12);  FMAG(bufA, 0);
                LOADQ(bufA, 16);  FMAG(bufB, 8);  ACCUM(1);
                LOADQ(bufB, 20);  FMAG(bufA, 0);
                LOADQ(bufA, 24);  FMAG(bufB, 8);  ACCUM(2);
                LOADQ(bufB, 28);  FMAG(bufA, 0);
                                  FMAG(bufB, 8);  ACCUM(3);
            }

            // Epilogue: unpack d-pairs -> two float4 rows per dp
#pragma unroll
            for (int dpl = 0; dpl < 4; ++dpl) {
                const int dp = dbase + dpl;
                const float4 o0 = make_float4(
                    ulo(acc[dpl * 4 + 0]), ulo(acc[dpl * 4 + 1]),
                    ulo(acc[dpl * 4 + 2]), ulo(acc[dpl * 4 + 3]));
                const float4 o1 = make_float4(
                    uhi(acc[dpl * 4 + 0]), uhi(acc[dpl * 4 + 1]),
                    uhi(acc[dpl * 4 + 2]), uhi(acc[dpl * 4 + 3]));
                og4[(dp * 2) * 32 + lane]     = o0;
                og4[(dp * 2 + 1) * 32 + lane] = o1;
            }
        }
    }
}

extern "C" void kernel_launch(void* const* d_in, const int* in_sizes, int n_in,
                              void* d_out, int out_size) {
    const float* x   = (const float*)d_in[0];
    const float* y   = (const float*)d_in[1];
    const float* cgc = (const float*)d_in[2];
    float* out = (float*)d_out;

    const int n_bm = in_sizes[0] / TILE_FLOATS;   // 4096

    tp_dense_kernel<<<GRID_BLOCKS, THREADS>>>(x, y, cgc, out, n_bm);
}